// round 14
// baseline (speedup 1.0000x reference)
#include <cuda_runtime.h>
#include <cuda_fp16.h>

#define NN    100000
#define EE    1600000
#define NADJ  4
#define DD    64
#define SLACK 64                      // bucket slots per row; P(deg>64)~1e-19

#define BUILD_BLKX ((EE + 255) / 256) // 6250; also 16 gemm rows per block
#define GATHER_BLKS (NN / 16)         // 2 rows/warp, 8 warps/block -> 6250

// ---------------- device scratch (static globals; no allocs allowed) ------
// g_edges: BSS-zeroed. Slots >= cnt are NEVER written; a zero slot decodes as
// (byte-offset 0, val 0.0f) == null edge contributing exactly 0.
// g_cnt: zeroed at end of final_kernel each run (replay-invariant).
__device__ __align__(16) __half2 g_h [(size_t)NN * 32];   // s0 (fp16 storage)
__device__ __align__(16) __half2 g_s1[(size_t)NN * 32];   // s1 (fp16 storage)
__device__ __align__(16) float2  g_edges[(size_t)NADJ * NN * SLACK]; // bucketed
__device__ int g_cnt[NADJ * NN];

// used-adjacency predicate (6 cached loads)
__device__ __forceinline__ bool adj_used(int a, const int* __restrict__ iq,
                                         const int* __restrict__ ir) {
    return __ldg(iq + 0) == a || __ldg(iq + 1) == a ||
           __ldg(iq + 2) == a || __ldg(iq + 3) == a ||
           __ldg(ir + 0) == a || __ldg(ir + 1) == a;
}

// ---------------- fused bucket-build + register GEMM (no smem) --------------
// blockIdx.y in [0, NADJ): single-pass edge bucketing for adjacency y.
// blockIdx.y == NADJ:      GEMM h = x@W + b, warp-per-row, W via L1.
__global__ void __launch_bounds__(256, 8)
build_gemm_kernel(const int* __restrict__ rows,
                  const int* __restrict__ cols,
                  const float* __restrict__ vals,
                  const float* __restrict__ x,
                  const float* __restrict__ Wm,
                  const float* __restrict__ b,
                  const int* __restrict__ iq,
                  const int* __restrict__ ir) {
    int tid = threadIdx.x;

    if (blockIdx.y < NADJ) {
        int a = blockIdx.y;
        if (!adj_used(a, iq, ir)) return;
        int e = blockIdx.x * blockDim.x + tid;
        if (e < EE) {
            size_t idx = (size_t)a * EE + e;
            int   r = rows[idx];
            int   c = cols[idx];
            float v = vals[idx];
            int   p = atomicAdd(&g_cnt[a * NN + r], 1);
            p = min(p, SLACK - 1);   // structurally unreachable; guards memory
            g_edges[((size_t)a * NN + r) * SLACK + p] =
                make_float2(__int_as_float(c << 7), v);   // byte offset of row
        }
        return;
    }

    // ---- GEMM: warp computes one row; lane l owns cols 2l, 2l+1 ----
    int wid  = tid >> 5;
    int lane = tid & 31;
    int rowBase = blockIdx.x * 16 + wid * 2;      // 6250*16 = 100000 rows
    float2 bv = __ldg((const float2*)b + lane);
    #pragma unroll
    for (int rr = 0; rr < 2; rr++) {
        int r = rowBase + rr;                      // always < NN
        float4 xv = __ldg((const float4*)x + (size_t)r * 16 + (lane & 15));
        float accx = 0.f, accy = 0.f;
        #pragma unroll
        for (int s = 0; s < 16; s++) {
            float xk0 = __shfl_sync(0xffffffffu, xv.x, s);
            float xk1 = __shfl_sync(0xffffffffu, xv.y, s);
            float xk2 = __shfl_sync(0xffffffffu, xv.z, s);
            float xk3 = __shfl_sync(0xffffffffu, xv.w, s);
            float2 w0 = __ldg((const float2*)(Wm + (4 * s + 0) * 64) + lane);
            float2 w1 = __ldg((const float2*)(Wm + (4 * s + 1) * 64) + lane);
            float2 w2 = __ldg((const float2*)(Wm + (4 * s + 2) * 64) + lane);
            float2 w3 = __ldg((const float2*)(Wm + (4 * s + 3) * 64) + lane);
            accx = fmaf(xk0, w0.x, accx); accy = fmaf(xk0, w0.y, accy);
            accx = fmaf(xk1, w1.x, accx); accy = fmaf(xk1, w1.y, accy);
            accx = fmaf(xk2, w2.x, accx); accy = fmaf(xk2, w2.y, accy);
            accx = fmaf(xk3, w3.x, accx); accy = fmaf(xk3, w3.y, accy);
        }
        g_h[(size_t)r * 32 + lane] = __floats2half2_rn(accx + bv.x, accy + bv.y);
    }
}

// ---------------- gather SpMM core: 2 rows per warp, unpredicated -----------
// Lanes 0-15: row 2w; lanes 16-31: row 2w+1. 4 cols/lane (LDG.64 of 2 half2).
// Edge list read via LDG.128 (2 edges/load). Loop runs to round_up4(warp-max);
// tail slots are BSS-null edges (offset 0, val 0) -> exact no-ops.
__device__ __forceinline__ void accum_dual(int a, int row,
                                           const __half2* __restrict__ src,
                                           unsigned subOff, float4& acc) {
    const float4* __restrict__ ed4 =
        (const float4*)(g_edges + ((size_t)a * NN + row) * SLACK);
    const char* __restrict__ base = (const char*)src + subOff;
    int end  = min(__ldg(&g_cnt[a * NN + row]), SLACK);
    int wmax = max(end, __shfl_xor_sync(0xffffffffu, end, 16));
    int iters = (wmax + 3) >> 2;                 // 4 edges per iteration
    for (int i = 0; i < iters; i++) {
        float4 eA = ed4[2 * i + 0];              // edges 0,1: (off,val,off,val)
        float4 eB = ed4[2 * i + 1];              // edges 2,3
        uint2 r0 = __ldg((const uint2*)(base + (unsigned)__float_as_int(eA.x)));
        uint2 r1 = __ldg((const uint2*)(base + (unsigned)__float_as_int(eA.z)));
        uint2 r2 = __ldg((const uint2*)(base + (unsigned)__float_as_int(eB.x)));
        uint2 r3 = __ldg((const uint2*)(base + (unsigned)__float_as_int(eB.z)));
        float2 p0 = __half22float2(*(__half2*)&r0.x), q0 = __half22float2(*(__half2*)&r0.y);
        float2 p1 = __half22float2(*(__half2*)&r1.x), q1 = __half22float2(*(__half2*)&r1.y);
        float2 p2 = __half22float2(*(__half2*)&r2.x), q2 = __half22float2(*(__half2*)&r2.y);
        float2 p3 = __half22float2(*(__half2*)&r3.x), q3 = __half22float2(*(__half2*)&r3.y);
        acc.x += eA.y * p0.x; acc.y += eA.y * p0.y; acc.z += eA.y * q0.x; acc.w += eA.y * q0.y;
        acc.x += eA.w * p1.x; acc.y += eA.w * p1.y; acc.z += eA.w * q1.x; acc.w += eA.w * q1.y;
        acc.x += eB.y * p2.x; acc.y += eB.y * p2.y; acc.z += eB.y * q2.x; acc.w += eB.y * q2.y;
        acc.x += eB.w * p3.x; acc.y += eB.w * p3.y; acc.z += eB.w * q3.x; acc.w += eB.w * q3.y;
    }
}

__device__ __forceinline__ float4 op_pair_dual(int a0, int a1, int row,
                                               const __half2* __restrict__ src,
                                               unsigned subOff) {
    float4 acc = make_float4(0.f, 0.f, 0.f, 0.f);
    accum_dual(a0, row, src, subOff, acc);
    if (a0 != a1) {
        accum_dual(a1, row, src, subOff, acc);
        acc.x *= 0.5f; acc.y *= 0.5f; acc.z *= 0.5f; acc.w *= 0.5f;
    }
    return acc;
}

// s1 = op_seq0(h)
__global__ void __launch_bounds__(256, 8)
spmm_mid_kernel(const int* __restrict__ idxes_seq) {
    int gw   = (blockIdx.x * blockDim.x + threadIdx.x) >> 5;   // warp id
    int lane = threadIdx.x & 31;
    int row  = 2 * gw + (lane >> 4);                           // < NN by grid
    int sub  = lane & 15;
    unsigned subOff = (unsigned)sub << 3;                      // sub*8 bytes
    float4 acc = op_pair_dual(__ldg(idxes_seq + 0), __ldg(idxes_seq + 1),
                              row, g_h, subOff);
    __half2 pk[2] = {__floats2half2_rn(acc.x, acc.y),
                     __floats2half2_rn(acc.z, acc.w)};
    ((uint2*)g_s1)[(size_t)row * 16 + sub] = *(uint2*)pk;
}

// s2 = op_seq1(s1) + op_res(h); LN; exact GELU; zero cnt for next replay
__global__ void __launch_bounds__(256, 8)
final_kernel(const int* __restrict__ idxes_seq,
             const int* __restrict__ idxes_res,
             const float* __restrict__ gamma,
             const float* __restrict__ beta,
             float* __restrict__ out) {
    int gw   = (blockIdx.x * blockDim.x + threadIdx.x) >> 5;
    int lane = threadIdx.x & 31;
    int row  = 2 * gw + (lane >> 4);
    int sub  = lane & 15;
    unsigned subOff = (unsigned)sub << 3;

    float4 a = op_pair_dual(__ldg(idxes_seq + 2), __ldg(idxes_seq + 3),
                            row, g_s1, subOff);
    float4 b = op_pair_dual(__ldg(idxes_res + 0), __ldg(idxes_res + 1),
                            row, g_h, subOff);
    a.x += b.x; a.y += b.y; a.z += b.z; a.w += b.w;

    // LayerNorm over 64 cols = 16 lanes x 4 vals (within half-warp)
    float s  = a.x + a.y + a.z + a.w;
    float ss = a.x * a.x + a.y * a.y + a.z * a.z + a.w * a.w;
    #pragma unroll
    for (int d = 8; d; d >>= 1) {
        s  += __shfl_xor_sync(0xffffffffu, s,  d);
        ss += __shfl_xor_sync(0xffffffffu, ss, d);
    }
    float mu   = s * (1.0f / 64.0f);
    float var  = ss * (1.0f / 64.0f) - mu * mu;
    float rstd = rsqrtf(var + 1e-5f);

    float4 g4 = ((const float4*)gamma)[sub];
    float4 b4 = ((const float4*)beta)[sub];
    float y0 = (a.x - mu) * rstd * g4.x + b4.x;
    float y1 = (a.y - mu) * rstd * g4.y + b4.y;
    float y2 = (a.z - mu) * rstd * g4.z + b4.z;
    float y3 = (a.w - mu) * rstd * g4.w + b4.w;
    const float k = 0.70710678118654752f;
    y0 = 0.5f * y0 * (1.0f + erff(y0 * k));
    y1 = 0.5f * y1 * (1.0f + erff(y1 * k));
    y2 = 0.5f * y2 * (1.0f + erff(y2 * k));
    y3 = 0.5f * y3 * (1.0f + erff(y3 * k));
    ((float4*)out)[(size_t)row * 16 + sub] = make_float4(y0, y1, y2, y3);

    // Zero counts for the next graph replay (this warp is the sole reader of
    // its rows' counts at this point; unused adjacencies stay 0).
    if (lane < 2 * NADJ) {
        int a_ = lane >> 1;
        int r_ = 2 * gw + (lane & 1);
        g_cnt[a_ * NN + r_] = 0;
    }
}

// ---------------- launch -----------------------------------------------------
extern "C" void kernel_launch(void* const* d_in, const int* in_sizes, int n_in,
                              void* d_out, int out_size) {
    const float* x         = (const float*)d_in[0];
    const float* W         = (const float*)d_in[1];
    const float* b         = (const float*)d_in[2];
    const int*   rows      = (const int*)  d_in[3];
    const int*   cols      = (const int*)  d_in[4];
    const float* vals      = (const float*)d_in[5];
    const float* gamma     = (const float*)d_in[6];
    const float* beta      = (const float*)d_in[7];
    const int*   idxes_seq = (const int*)  d_in[8];
    const int*   idxes_res = (const int*)  d_in[9];
    float*       out       = (float*)d_out;

    build_gemm_kernel<<<dim3(BUILD_BLKX, NADJ + 1), 256>>>(
        rows, cols, vals, x, W, b, idxes_seq, idxes_res);
    spmm_mid_kernel<<<GATHER_BLKS, 256>>>(idxes_seq);
    final_kernel<<<GATHER_BLKS, 256>>>(idxes_seq, idxes_res, gamma, beta, out);
}

// round 15
// speedup vs baseline: 1.0705x; 1.0705x over previous
#include <cuda_runtime.h>
#include <cuda_fp16.h>

#define NN    100000
#define EE    1600000
#define NADJ  4
#define DD    64
#define SLACK 64                      // bucket slots per row; P(deg>64)~1e-19

#define BUILD_BLKX ((EE + 255) / 256) // 6250
#define GEMM_BLKS  ((NN + 63) / 64)   // 1563
#define GATHER_BLKS (NN / 16)         // 2 rows/warp, 8 warps/block -> 6250

// ---------------- device scratch (static globals; no allocs allowed) ------
// g_edges: BSS-zeroed. Slots >= cnt are NEVER written; a zero slot decodes as
// (byte-offset 0, val 0.0f) == null edge contributing exactly 0.
// g_cnt: zeroed at end of final_kernel each run (replay-invariant).
__device__ __align__(16) __half2 g_h [(size_t)NN * 32];   // s0 (fp16 storage)
__device__ __align__(16) __half2 g_s1[(size_t)NN * 32];   // s1 (fp16 storage)
__device__ __align__(16) float2  g_edges[(size_t)NADJ * NN * SLACK]; // bucketed
__device__ int g_cnt[NADJ * NN];

// used-adjacency predicate (6 cached loads)
__device__ __forceinline__ bool adj_used(int a, const int* __restrict__ iq,
                                         const int* __restrict__ ir) {
    return __ldg(iq + 0) == a || __ldg(iq + 1) == a ||
           __ldg(iq + 2) == a || __ldg(iq + 3) == a ||
           __ldg(ir + 0) == a || __ldg(ir + 1) == a;
}

// ---------------- fused bucket-build + smem GEMM (R12 version) --------------
// blockIdx.y in [0, NADJ): single-pass edge bucketing for adjacency y.
// blockIdx.y == NADJ:      GEMM h = x@W + b (smem-tiled, 64x64).
__global__ void build_gemm_kernel(const int* __restrict__ rows,
                                  const int* __restrict__ cols,
                                  const float* __restrict__ vals,
                                  const float* __restrict__ x,
                                  const float* __restrict__ Wm,
                                  const float* __restrict__ b,
                                  const int* __restrict__ iq,
                                  const int* __restrict__ ir) {
    __shared__ float4 Ws4[64 * 16];
    __shared__ float  Xs[64 * 65];
    int tid = threadIdx.x;

    if (blockIdx.y < NADJ) {
        int a = blockIdx.y;
        if (!adj_used(a, iq, ir)) return;
        int e = blockIdx.x * blockDim.x + tid;
        if (e < EE) {
            size_t idx = (size_t)a * EE + e;
            int   r = rows[idx];
            int   c = cols[idx];
            float v = vals[idx];
            int   p = atomicAdd(&g_cnt[a * NN + r], 1);
            p = min(p, SLACK - 1);   // structurally unreachable; guards memory
            g_edges[((size_t)a * NN + r) * SLACK + p] =
                make_float2(__int_as_float(c << 7), v);   // byte offset of row
        }
        return;
    }

    // ---- GEMM part ----
    if (blockIdx.x >= GEMM_BLKS) return;
    for (int i = tid; i < 64 * 16; i += 256) Ws4[i] = ((const float4*)Wm)[i];
    int rowBase = blockIdx.x * 64;
    for (int i = tid; i < 1024; i += 256) {
        int r = i >> 4, c4 = i & 15;
        int grow = rowBase + r;
        float4 v = make_float4(0.f, 0.f, 0.f, 0.f);
        if (grow < NN) v = ((const float4*)x)[(size_t)grow * 16 + c4];
        int o = r * 65 + c4 * 4;
        Xs[o] = v.x; Xs[o + 1] = v.y; Xs[o + 2] = v.z; Xs[o + 3] = v.w;
    }
    __syncthreads();
    int tx = tid & 15, ty = tid >> 4;
    float4 a0 = make_float4(0.f,0.f,0.f,0.f), a1 = a0, a2 = a0, a3 = a0;
    #pragma unroll 8
    for (int k = 0; k < 64; k++) {
        float4 wv = Ws4[k * 16 + tx];
        float x0 = Xs[(ty * 4 + 0) * 65 + k];
        float x1 = Xs[(ty * 4 + 1) * 65 + k];
        float x2 = Xs[(ty * 4 + 2) * 65 + k];
        float x3 = Xs[(ty * 4 + 3) * 65 + k];
        a0.x += x0 * wv.x; a0.y += x0 * wv.y; a0.z += x0 * wv.z; a0.w += x0 * wv.w;
        a1.x += x1 * wv.x; a1.y += x1 * wv.y; a1.z += x1 * wv.z; a1.w += x1 * wv.w;
        a2.x += x2 * wv.x; a2.y += x2 * wv.y; a2.z += x2 * wv.z; a2.w += x2 * wv.w;
        a3.x += x3 * wv.x; a3.y += x3 * wv.y; a3.z += x3 * wv.z; a3.w += x3 * wv.w;
    }
    float4 bv = ((const float4*)b)[tx];
    float4 outs[4] = {a0, a1, a2, a3};
    int r0 = rowBase + ty * 4;
    #pragma unroll
    for (int i = 0; i < 4; i++) {
        int r = r0 + i;
        if (r < NN) {
            float4 o = outs[i];
            o.x += bv.x; o.y += bv.y; o.z += bv.z; o.w += bv.w;
            __half2 p0 = __floats2half2_rn(o.x, o.y);
            __half2 p1 = __floats2half2_rn(o.z, o.w);
            __half2 pk[2] = {p0, p1};
            ((uint2*)g_h)[(size_t)r * 16 + tx] = *(uint2*)pk;
        }
    }
}

// ---------------- gather SpMM core: 2 rows per warp, unpredicated -----------
// Lanes 0-15: row 2w; lanes 16-31: row 2w+1. 4 cols/lane (LDG.64 of 2 half2).
// Edge list read via LDG.128 (2 edges/load). Loop runs to round_up4(warp-max);
// tail slots are BSS-null edges (offset 0, val 0) -> exact no-ops.
__device__ __forceinline__ void accum_dual(int a, int row,
                                           const __half2* __restrict__ src,
                                           unsigned subOff, float4& acc) {
    const float4* __restrict__ ed4 =
        (const float4*)(g_edges + ((size_t)a * NN + row) * SLACK);
    const char* __restrict__ base = (const char*)src + subOff;
    int end  = min(__ldg(&g_cnt[a * NN + row]), SLACK);
    int wmax = max(end, __shfl_xor_sync(0xffffffffu, end, 16));
    int iters = (wmax + 3) >> 2;                 // 4 edges per iteration
    for (int i = 0; i < iters; i++) {
        float4 eA = ed4[2 * i + 0];              // edges 0,1: (off,val,off,val)
        float4 eB = ed4[2 * i + 1];              // edges 2,3
        uint2 r0 = __ldg((const uint2*)(base + (unsigned)__float_as_int(eA.x)));
        uint2 r1 = __ldg((const uint2*)(base + (unsigned)__float_as_int(eA.z)));
        uint2 r2 = __ldg((const uint2*)(base + (unsigned)__float_as_int(eB.x)));
        uint2 r3 = __ldg((const uint2*)(base + (unsigned)__float_as_int(eB.z)));
        float2 p0 = __half22float2(*(__half2*)&r0.x), q0 = __half22float2(*(__half2*)&r0.y);
        float2 p1 = __half22float2(*(__half2*)&r1.x), q1 = __half22float2(*(__half2*)&r1.y);
        float2 p2 = __half22float2(*(__half2*)&r2.x), q2 = __half22float2(*(__half2*)&r2.y);
        float2 p3 = __half22float2(*(__half2*)&r3.x), q3 = __half22float2(*(__half2*)&r3.y);
        acc.x += eA.y * p0.x; acc.y += eA.y * p0.y; acc.z += eA.y * q0.x; acc.w += eA.y * q0.y;
        acc.x += eA.w * p1.x; acc.y += eA.w * p1.y; acc.z += eA.w * q1.x; acc.w += eA.w * q1.y;
        acc.x += eB.y * p2.x; acc.y += eB.y * p2.y; acc.z += eB.y * q2.x; acc.w += eB.y * q2.y;
        acc.x += eB.w * p3.x; acc.y += eB.w * p3.y; acc.z += eB.w * q3.x; acc.w += eB.w * q3.y;
    }
}

__device__ __forceinline__ float4 op_pair_dual(int a0, int a1, int row,
                                               const __half2* __restrict__ src,
                                               unsigned subOff) {
    float4 acc = make_float4(0.f, 0.f, 0.f, 0.f);
    accum_dual(a0, row, src, subOff, acc);
    if (a0 != a1) {
        accum_dual(a1, row, src, subOff, acc);
        acc.x *= 0.5f; acc.y *= 0.5f; acc.z *= 0.5f; acc.w *= 0.5f;
    }
    return acc;
}

// s1 = op_seq0(h)
__global__ void __launch_bounds__(256, 8)
spmm_mid_kernel(const int* __restrict__ idxes_seq) {
    int gw   = (blockIdx.x * blockDim.x + threadIdx.x) >> 5;   // warp id
    int lane = threadIdx.x & 31;
    int row  = 2 * gw + (lane >> 4);                           // < NN by grid
    int sub  = lane & 15;
    unsigned subOff = (unsigned)sub << 3;                      // sub*8 bytes
    float4 acc = op_pair_dual(__ldg(idxes_seq + 0), __ldg(idxes_seq + 1),
                              row, g_h, subOff);
    __half2 pk[2] = {__floats2half2_rn(acc.x, acc.y),
                     __floats2half2_rn(acc.z, acc.w)};
    ((uint2*)g_s1)[(size_t)row * 16 + sub] = *(uint2*)pk;
}

// s2 = op_seq1(s1) + op_res(h); LN; exact GELU; zero cnt for next replay
__global__ void __launch_bounds__(256, 8)
final_kernel(const int* __restrict__ idxes_seq,
             const int* __restrict__ idxes_res,
             const float* __restrict__ gamma,
             const float* __restrict__ beta,
             float* __restrict__ out) {
    int gw   = (blockIdx.x * blockDim.x + threadIdx.x) >> 5;
    int lane = threadIdx.x & 31;
    int row  = 2 * gw + (lane >> 4);
    int sub  = lane & 15;
    unsigned subOff = (unsigned)sub << 3;

    float4 a = op_pair_dual(__ldg(idxes_seq + 2), __ldg(idxes_seq + 3),
                            row, g_s1, subOff);
    float4 b = op_pair_dual(__ldg(idxes_res + 0), __ldg(idxes_res + 1),
                            row, g_h, subOff);
    a.x += b.x; a.y += b.y; a.z += b.z; a.w += b.w;

    // LayerNorm over 64 cols = 16 lanes x 4 vals (within half-warp)
    float s  = a.x + a.y + a.z + a.w;
    float ss = a.x * a.x + a.y * a.y + a.z * a.z + a.w * a.w;
    #pragma unroll
    for (int d = 8; d; d >>= 1) {
        s  += __shfl_xor_sync(0xffffffffu, s,  d);
        ss += __shfl_xor_sync(0xffffffffu, ss, d);
    }
    float mu   = s * (1.0f / 64.0f);
    float var  = ss * (1.0f / 64.0f) - mu * mu;
    float rstd = rsqrtf(var + 1e-5f);

    float4 g4 = ((const float4*)gamma)[sub];
    float4 b4 = ((const float4*)beta)[sub];
    float y0 = (a.x - mu) * rstd * g4.x + b4.x;
    float y1 = (a.y - mu) * rstd * g4.y + b4.y;
    float y2 = (a.z - mu) * rstd * g4.z + b4.z;
    float y3 = (a.w - mu) * rstd * g4.w + b4.w;
    const float k = 0.70710678118654752f;
    y0 = 0.5f * y0 * (1.0f + erff(y0 * k));
    y1 = 0.5f * y1 * (1.0f + erff(y1 * k));
    y2 = 0.5f * y2 * (1.0f + erff(y2 * k));
    y3 = 0.5f * y3 * (1.0f + erff(y3 * k));
    ((float4*)out)[(size_t)row * 16 + sub] = make_float4(y0, y1, y2, y3);

    // Zero counts for the next graph replay (this warp is the sole reader of
    // its rows' counts at this point; unused adjacencies stay 0).
    if (lane < 2 * NADJ) {
        int a_ = lane >> 1;
        int r_ = 2 * gw + (lane & 1);
        g_cnt[a_ * NN + r_] = 0;
    }
}

// ---------------- launch -----------------------------------------------------
extern "C" void kernel_launch(void* const* d_in, const int* in_sizes, int n_in,
                              void* d_out, int out_size) {
    const float* x         = (const float*)d_in[0];
    const float* W         = (const float*)d_in[1];
    const float* b         = (const float*)d_in[2];
    const int*   rows      = (const int*)  d_in[3];
    const int*   cols      = (const int*)  d_in[4];
    const float* vals      = (const float*)d_in[5];
    const float* gamma     = (const float*)d_in[6];
    const float* beta      = (const float*)d_in[7];
    const int*   idxes_seq = (const int*)  d_in[8];
    const int*   idxes_res = (const int*)  d_in[9];
    float*       out       = (float*)d_out;

    build_gemm_kernel<<<dim3(BUILD_BLKX, NADJ + 1), 256>>>(
        rows, cols, vals, x, W, b, idxes_seq, idxes_res);
    spmm_mid_kernel<<<GATHER_BLKS, 256>>>(idxes_seq);
    final_kernel<<<GATHER_BLKS, 256>>>(idxes_seq, idxes_res, gamma, beta, out);
}

// round 16
// speedup vs baseline: 1.1255x; 1.0514x over previous
#include <cuda_runtime.h>
#include <cuda_fp16.h>

#define NN    100000
#define EE    1600000
#define NADJ  4
#define DD    64
#define SLACK 64                      // bucket slots per row; P(deg>64)~1e-19

#define QUADS      (EE / 4)           // 400000 edge-quads per adjacency
#define BUILD_BLKX ((QUADS + 255) / 256) // 1563
#define GEMM_BLKS  ((NN + 63) / 64)   // 1563 (== BUILD_BLKX)
#define GATHER_BLKS (NN / 16)         // 2 rows/warp, 8 warps/block -> 6250

// ---------------- device scratch (static globals; no allocs allowed) ------
// g_edges: BSS-zeroed. Slots >= cnt are NEVER written; a zero slot decodes as
// (byte-offset 0, val 0.0f) == null edge contributing exactly 0.
// g_cnt: zeroed at end of final_kernel each run (replay-invariant).
__device__ __align__(16) __half2 g_h [(size_t)NN * 32];   // s0 (fp16 storage)
__device__ __align__(16) __half2 g_s1[(size_t)NN * 32];   // s1 (fp16 storage)
__device__ __align__(16) float2  g_edges[(size_t)NADJ * NN * SLACK]; // bucketed
__device__ int g_cnt[NADJ * NN];

// used-adjacency predicate (6 cached loads)
__device__ __forceinline__ bool adj_used(int a, const int* __restrict__ iq,
                                         const int* __restrict__ ir) {
    return __ldg(iq + 0) == a || __ldg(iq + 1) == a ||
           __ldg(iq + 2) == a || __ldg(iq + 3) == a ||
           __ldg(ir + 0) == a || __ldg(ir + 1) == a;
}

// ---------------- fused bucket-build (4 chains/thread) + smem GEMM ----------
// blockIdx.y in [0, NADJ): bucketing for adjacency y, 4 edges per thread via
//   LDG.128 quad loads -> 4 independent atomicAdd->STG chains (MLP=4).
// blockIdx.y == NADJ:      GEMM h = x@W + b (smem-tiled, 64x64).
__global__ void build_gemm_kernel(const int* __restrict__ rows,
                                  const int* __restrict__ cols,
                                  const float* __restrict__ vals,
                                  const float* __restrict__ x,
                                  const float* __restrict__ Wm,
                                  const float* __restrict__ b,
                                  const int* __restrict__ iq,
                                  const int* __restrict__ ir) {
    __shared__ float4 Ws4[64 * 16];
    __shared__ float  Xs[64 * 65];
    int tid = threadIdx.x;

    if (blockIdx.y < NADJ) {
        int a = blockIdx.y;
        if (!adj_used(a, iq, ir)) return;
        int q = blockIdx.x * blockDim.x + tid;
        if (q < QUADS) {
            size_t eb = (size_t)a * EE + (size_t)q * 4;   // 16B-aligned (EE%4==0)
            int4   r4 = *(const int4*)  (rows + eb);
            int4   c4 = *(const int4*)  (cols + eb);
            float4 v4 = *(const float4*)(vals + eb);
            // 4 independent atomic->store chains; ptxas front-batches the atomics
            int p0 = atomicAdd(&g_cnt[a * NN + r4.x], 1);
            int p1 = atomicAdd(&g_cnt[a * NN + r4.y], 1);
            int p2 = atomicAdd(&g_cnt[a * NN + r4.z], 1);
            int p3 = atomicAdd(&g_cnt[a * NN + r4.w], 1);
            p0 = min(p0, SLACK - 1); p1 = min(p1, SLACK - 1);
            p2 = min(p2, SLACK - 1); p3 = min(p3, SLACK - 1);
            g_edges[((size_t)a * NN + r4.x) * SLACK + p0] =
                make_float2(__int_as_float(c4.x << 7), v4.x);
            g_edges[((size_t)a * NN + r4.y) * SLACK + p1] =
                make_float2(__int_as_float(c4.y << 7), v4.y);
            g_edges[((size_t)a * NN + r4.z) * SLACK + p2] =
                make_float2(__int_as_float(c4.z << 7), v4.z);
            g_edges[((size_t)a * NN + r4.w) * SLACK + p3] =
                make_float2(__int_as_float(c4.w << 7), v4.w);
        }
        return;
    }

    // ---- GEMM part ----
    if (blockIdx.x >= GEMM_BLKS) return;
    for (int i = tid; i < 64 * 16; i += 256) Ws4[i] = ((const float4*)Wm)[i];
    int rowBase = blockIdx.x * 64;
    for (int i = tid; i < 1024; i += 256) {
        int r = i >> 4, c4 = i & 15;
        int grow = rowBase + r;
        float4 v = make_float4(0.f, 0.f, 0.f, 0.f);
        if (grow < NN) v = ((const float4*)x)[(size_t)grow * 16 + c4];
        int o = r * 65 + c4 * 4;
        Xs[o] = v.x; Xs[o + 1] = v.y; Xs[o + 2] = v.z; Xs[o + 3] = v.w;
    }
    __syncthreads();
    int tx = tid & 15, ty = tid >> 4;
    float4 a0 = make_float4(0.f,0.f,0.f,0.f), a1 = a0, a2 = a0, a3 = a0;
    #pragma unroll 8
    for (int k = 0; k < 64; k++) {
        float4 wv = Ws4[k * 16 + tx];
        float x0 = Xs[(ty * 4 + 0) * 65 + k];
        float x1 = Xs[(ty * 4 + 1) * 65 + k];
        float x2 = Xs[(ty * 4 + 2) * 65 + k];
        float x3 = Xs[(ty * 4 + 3) * 65 + k];
        a0.x += x0 * wv.x; a0.y += x0 * wv.y; a0.z += x0 * wv.z; a0.w += x0 * wv.w;
        a1.x += x1 * wv.x; a1.y += x1 * wv.y; a1.z += x1 * wv.z; a1.w += x1 * wv.w;
        a2.x += x2 * wv.x; a2.y += x2 * wv.y; a2.z += x2 * wv.z; a2.w += x2 * wv.w;
        a3.x += x3 * wv.x; a3.y += x3 * wv.y; a3.z += x3 * wv.z; a3.w += x3 * wv.w;
    }
    float4 bv = ((const float4*)b)[tx];
    float4 outs[4] = {a0, a1, a2, a3};
    int r0 = rowBase + ty * 4;
    #pragma unroll
    for (int i = 0; i < 4; i++) {
        int r = r0 + i;
        if (r < NN) {
            float4 o = outs[i];
            o.x += bv.x; o.y += bv.y; o.z += bv.z; o.w += bv.w;
            __half2 p0 = __floats2half2_rn(o.x, o.y);
            __half2 p1 = __floats2half2_rn(o.z, o.w);
            __half2 pk[2] = {p0, p1};
            ((uint2*)g_h)[(size_t)r * 16 + tx] = *(uint2*)pk;
        }
    }
}

// ---------------- gather SpMM core: 2 rows per warp, unpredicated -----------
// Lanes 0-15: row 2w; lanes 16-31: row 2w+1. 4 cols/lane (LDG.64 of 2 half2).
// Edge list read via LDG.128 (2 edges/load). Loop runs to round_up4(warp-max);
// tail slots are BSS-null edges (offset 0, val 0) -> exact no-ops.
__device__ __forceinline__ void accum_dual(int a, int row,
                                           const __half2* __restrict__ src,
                                           unsigned subOff, float4& acc) {
    const float4* __restrict__ ed4 =
        (const float4*)(g_edges + ((size_t)a * NN + row) * SLACK);
    const char* __restrict__ base = (const char*)src + subOff;
    int end  = min(__ldg(&g_cnt[a * NN + row]), SLACK);
    int wmax = max(end, __shfl_xor_sync(0xffffffffu, end, 16));
    int iters = (wmax + 3) >> 2;                 // 4 edges per iteration
    for (int i = 0; i < iters; i++) {
        float4 eA = ed4[2 * i + 0];              // edges 0,1: (off,val,off,val)
        float4 eB = ed4[2 * i + 1];              // edges 2,3
        uint2 r0 = __ldg((const uint2*)(base + (unsigned)__float_as_int(eA.x)));
        uint2 r1 = __ldg((const uint2*)(base + (unsigned)__float_as_int(eA.z)));
        uint2 r2 = __ldg((const uint2*)(base + (unsigned)__float_as_int(eB.x)));
        uint2 r3 = __ldg((const uint2*)(base + (unsigned)__float_as_int(eB.z)));
        float2 p0 = __half22float2(*(__half2*)&r0.x), q0 = __half22float2(*(__half2*)&r0.y);
        float2 p1 = __half22float2(*(__half2*)&r1.x), q1 = __half22float2(*(__half2*)&r1.y);
        float2 p2 = __half22float2(*(__half2*)&r2.x), q2 = __half22float2(*(__half2*)&r2.y);
        float2 p3 = __half22float2(*(__half2*)&r3.x), q3 = __half22float2(*(__half2*)&r3.y);
        acc.x += eA.y * p0.x; acc.y += eA.y * p0.y; acc.z += eA.y * q0.x; acc.w += eA.y * q0.y;
        acc.x += eA.w * p1.x; acc.y += eA.w * p1.y; acc.z += eA.w * q1.x; acc.w += eA.w * q1.y;
        acc.x += eB.y * p2.x; acc.y += eB.y * p2.y; acc.z += eB.y * q2.x; acc.w += eB.y * q2.y;
        acc.x += eB.w * p3.x; acc.y += eB.w * p3.y; acc.z += eB.w * q3.x; acc.w += eB.w * q3.y;
    }
}

__device__ __forceinline__ float4 op_pair_dual(int a0, int a1, int row,
                                               const __half2* __restrict__ src,
                                               unsigned subOff) {
    float4 acc = make_float4(0.f, 0.f, 0.f, 0.f);
    accum_dual(a0, row, src, subOff, acc);
    if (a0 != a1) {
        accum_dual(a1, row, src, subOff, acc);
        acc.x *= 0.5f; acc.y *= 0.5f; acc.z *= 0.5f; acc.w *= 0.5f;
    }
    return acc;
}

// s1 = op_seq0(h)
__global__ void __launch_bounds__(256, 8)
spmm_mid_kernel(const int* __restrict__ idxes_seq) {
    int gw   = (blockIdx.x * blockDim.x + threadIdx.x) >> 5;   // warp id
    int lane = threadIdx.x & 31;
    int row  = 2 * gw + (lane >> 4);                           // < NN by grid
    int sub  = lane & 15;
    unsigned subOff = (unsigned)sub << 3;                      // sub*8 bytes
    float4 acc = op_pair_dual(__ldg(idxes_seq + 0), __ldg(idxes_seq + 1),
                              row, g_h, subOff);
    __half2 pk[2] = {__floats2half2_rn(acc.x, acc.y),
                     __floats2half2_rn(acc.z, acc.w)};
    ((uint2*)g_s1)[(size_t)row * 16 + sub] = *(uint2*)pk;
}

// s2 = op_seq1(s1) + op_res(h); LN; exact GELU; zero cnt for next replay
__global__ void __launch_bounds__(256, 8)
final_kernel(const int* __restrict__ idxes_seq,
             const int* __restrict__ idxes_res,
             const float* __restrict__ gamma,
             const float* __restrict__ beta,
             float* __restrict__ out) {
    int gw   = (blockIdx.x * blockDim.x + threadIdx.x) >> 5;
    int lane = threadIdx.x & 31;
    int row  = 2 * gw + (lane >> 4);
    int sub  = lane & 15;
    unsigned subOff = (unsigned)sub << 3;

    float4 a = op_pair_dual(__ldg(idxes_seq + 2), __ldg(idxes_seq + 3),
                            row, g_s1, subOff);
    float4 b = op_pair_dual(__ldg(idxes_res + 0), __ldg(idxes_res + 1),
                            row, g_h, subOff);
    a.x += b.x; a.y += b.y; a.z += b.z; a.w += b.w;

    // LayerNorm over 64 cols = 16 lanes x 4 vals (within half-warp)
    float s  = a.x + a.y + a.z + a.w;
    float ss = a.x * a.x + a.y * a.y + a.z * a.z + a.w * a.w;
    #pragma unroll
    for (int d = 8; d; d >>= 1) {
        s  += __shfl_xor_sync(0xffffffffu, s,  d);
        ss += __shfl_xor_sync(0xffffffffu, ss, d);
    }
    float mu   = s * (1.0f / 64.0f);
    float var  = ss * (1.0f / 64.0f) - mu * mu;
    float rstd = rsqrtf(var + 1e-5f);

    float4 g4 = ((const float4*)gamma)[sub];
    float4 b4 = ((const float4*)beta)[sub];
    float y0 = (a.x - mu) * rstd * g4.x + b4.x;
    float y1 = (a.y - mu) * rstd * g4.y + b4.y;
    float y2 = (a.z - mu) * rstd * g4.z + b4.z;
    float y3 = (a.w - mu) * rstd * g4.w + b4.w;
    const float k = 0.70710678118654752f;
    y0 = 0.5f * y0 * (1.0f + erff(y0 * k));
    y1 = 0.5f * y1 * (1.0f + erff(y1 * k));
    y2 = 0.5f * y2 * (1.0f + erff(y2 * k));
    y3 = 0.5f * y3 * (1.0f + erff(y3 * k));
    ((float4*)out)[(size_t)row * 16 + sub] = make_float4(y0, y1, y2, y3);

    // Zero counts for the next graph replay (this warp is the sole reader of
    // its rows' counts at this point; unused adjacencies stay 0).
    if (lane < 2 * NADJ) {
        int a_ = lane >> 1;
        int r_ = 2 * gw + (lane & 1);
        g_cnt[a_ * NN + r_] = 0;
    }
}

// ---------------- launch -----------------------------------------------------
extern "C" void kernel_launch(void* const* d_in, const int* in_sizes, int n_in,
                              void* d_out, int out_size) {
    const float* x         = (const float*)d_in[0];
    const float* W         = (const float*)d_in[1];
    const float* b         = (const float*)d_in[2];
    const int*   rows      = (const int*)  d_in[3];
    const int*   cols      = (const int*)  d_in[4];
    const float* vals      = (const float*)d_in[5];
    const float* gamma     = (const float*)d_in[6];
    const float* beta      = (const float*)d_in[7];
    const int*   idxes_seq = (const int*)  d_in[8];
    const int*   idxes_res = (const int*)  d_in[9];
    float*       out       = (float*)d_out;

    build_gemm_kernel<<<dim3(BUILD_BLKX, NADJ + 1), 256>>>(
        rows, cols, vals, x, W, b, idxes_seq, idxes_res);
    spmm_mid_kernel<<<GATHER_BLKS, 256>>>(idxes_seq);
    final_kernel<<<GATHER_BLKS, 256>>>(idxes_seq, idxes_res, gamma, beta, out);
}